// round 1
// baseline (speedup 1.0000x reference)
#include <cuda_runtime.h>
#include <cstdint>

#define HIDDEN 128
#define RAYS_PER_BLOCK 128

// ---------------------------------------------------------------------------
// Packed f32x2 helpers (Blackwell). ptxas never auto-fuses 2x fmaf into FFMA2;
// only the PTX fma.rn.f32x2 path reaches the double-rate packed fp32 pipe.
// ---------------------------------------------------------------------------
static __device__ __forceinline__ unsigned long long ffma2(
    unsigned long long a, unsigned long long b, unsigned long long c) {
    unsigned long long d;
    asm("fma.rn.f32x2 %0, %1, %2, %3;" : "=l"(d) : "l"(a), "l"(b), "l"(c));
    return d;
}

static __device__ __forceinline__ unsigned long long pack2(float lo, float hi) {
    unsigned long long r;
    asm("mov.b64 %0, {%1, %2};" : "=l"(r) : "f"(lo), "f"(hi));
    return r;
}

static __device__ __forceinline__ void unpack2(unsigned long long v, float& lo, float& hi) {
    asm("mov.b64 {%0, %1}, %2;" : "=f"(lo), "=f"(hi) : "l"(v));
}

// Shared memory layout (dynamic, ~68.6 KB):
//   [0)                 w2t[128][128]  W2 transposed: w2t[j][i] = W2[i][j]
//   [16384)             w1[3*128]      W1 as given (row-major [3][128])
//   [16768)             b1[128]
//   [16896)             b2[128]
//   [17024)             w3[128]
//   [17152)             b3
static constexpr int SMEM_FLOATS = HIDDEN * HIDDEN + 3 * HIDDEN + HIDDEN + HIDDEN + HIDDEN + 4;

extern __shared__ float s_mem[];

__global__ void __launch_bounds__(RAYS_PER_BLOCK, 2)
sdf_march_kernel(const float* __restrict__ pos,
                 const float* __restrict__ dir,
                 const float* __restrict__ W1,
                 const float* __restrict__ b1,
                 const float* __restrict__ W2,
                 const float* __restrict__ b2,
                 const float* __restrict__ W3,
                 const float* __restrict__ b3,
                 const int* __restrict__ steps_ptr,
                 float* __restrict__ out) {
    float* s_w2t = s_mem;                    // 16384
    float* s_w1  = s_w2t + HIDDEN * HIDDEN;  // 384
    float* s_b1  = s_w1 + 3 * HIDDEN;        // 128
    float* s_b2  = s_b1 + HIDDEN;            // 128
    float* s_w3  = s_b2 + HIDDEN;            // 128
    float* s_b3  = s_w3 + HIDDEN;            // 1

    const int t = threadIdx.x;

    // Load W2 transposed. Reads are coalesced (consecutive t -> consecutive
    // gmem addresses); store conflicts are a one-time cost.
    #pragma unroll 4
    for (int i = 0; i < HIDDEN; ++i) {
        s_w2t[t * HIDDEN + i] = W2[i * HIDDEN + t];
    }
    #pragma unroll
    for (int k = t; k < 3 * HIDDEN; k += RAYS_PER_BLOCK) s_w1[k] = W1[k];
    s_b1[t] = b1[t];
    s_b2[t] = b2[t];
    s_w3[t] = W3[t];
    if (t == 0) s_b3[0] = b3[0];
    __syncthreads();

    const int ray = blockIdx.x * RAYS_PER_BLOCK + t;
    float px = pos[ray * 3 + 0];
    float py = pos[ray * 3 + 1];
    float pz = pos[ray * 3 + 2];
    const float dx = dir[ray * 3 + 0];
    const float dy = dir[ray * 3 + 1];
    const float dz = dir[ray * 3 + 2];

    const int n_steps = steps_ptr[0];
    const float bias3 = s_b3[0];

    // h1 for this ray, packed 2 floats per 64-bit register: h1u[k] = (h1[2k], h1[2k+1])
    unsigned long long h1u[HIDDEN / 2];

    for (int s = 0; s < n_steps; ++s) {
        // ---- Layer 1: h1 = relu(p @ W1 + b1), 3 MACs per output ----
        #pragma unroll
        for (int k = 0; k < HIDDEN / 2; ++k) {
            const int j0 = 2 * k;
            const int j1 = 2 * k + 1;
            float a = fmaf(px, s_w1[j0],
                      fmaf(py, s_w1[HIDDEN + j0],
                      fmaf(pz, s_w1[2 * HIDDEN + j0], s_b1[j0])));
            float b = fmaf(px, s_w1[j1],
                      fmaf(py, s_w1[HIDDEN + j1],
                      fmaf(pz, s_w1[2 * HIDDEN + j1], s_b1[j1])));
            a = fmaxf(a, 0.0f);
            b = fmaxf(b, 0.0f);
            h1u[k] = pack2(a, b);
        }

        // ---- Layers 2+3 fused: sdf = W3 . relu(h1 @ W2 + b2) + b3 ----
        // Per output j: contiguous LDS.128 broadcast of W2^T row, two
        // independent FFMA2 chains (ILP for lat4/rt2 saturation).
        float sdf = bias3;
        #pragma unroll 2
        for (int j = 0; j < HIDDEN; ++j) {
            const ulonglong2* wrow =
                reinterpret_cast<const ulonglong2*>(s_w2t + j * HIDDEN);
            unsigned long long acc0 = pack2(s_b2[j], 0.0f);
            unsigned long long acc1 = pack2(0.0f, 0.0f);
            #pragma unroll
            for (int m = 0; m < HIDDEN / 4; ++m) {
                const ulonglong2 w = wrow[m];            // floats [4m .. 4m+3]
                acc0 = ffma2(h1u[2 * m],     w.x, acc0); // i = 4m, 4m+1
                acc1 = ffma2(h1u[2 * m + 1], w.y, acc1); // i = 4m+2, 4m+3
            }
            float l0, h0, l1, h1v;
            unpack2(acc0, l0, h0);
            unpack2(acc1, l1, h1v);
            const float h2 = (l0 + h0) + (l1 + h1v);
            sdf = fmaf(fmaxf(h2, 0.0f), s_w3[j], sdf);
        }

        // ---- March ----
        px = fmaf(sdf, dx, px);
        py = fmaf(sdf, dy, py);
        pz = fmaf(sdf, dz, pz);
    }

    out[ray * 3 + 0] = px;
    out[ray * 3 + 1] = py;
    out[ray * 3 + 2] = pz;
}

extern "C" void kernel_launch(void* const* d_in, const int* in_sizes, int n_in,
                              void* d_out, int out_size) {
    const float* pos = (const float*)d_in[0];
    const float* dir = (const float*)d_in[1];
    const float* W1  = (const float*)d_in[2];
    const float* b1  = (const float*)d_in[3];
    const float* W2  = (const float*)d_in[4];
    const float* b2  = (const float*)d_in[5];
    const float* W3  = (const float*)d_in[6];
    const float* b3  = (const float*)d_in[7];
    const int* steps = (const int*)d_in[8];

    const int n_rays = in_sizes[0] / 3;
    const int n_blocks = n_rays / RAYS_PER_BLOCK;

    const size_t smem_bytes = SMEM_FLOATS * sizeof(float);
    cudaFuncSetAttribute(sdf_march_kernel,
                         cudaFuncAttributeMaxDynamicSharedMemorySize,
                         (int)smem_bytes);

    sdf_march_kernel<<<n_blocks, RAYS_PER_BLOCK, smem_bytes>>>(
        pos, dir, W1, b1, W2, b2, W3, b3, steps, (float*)d_out);
}

// round 3
// speedup vs baseline: 1.5401x; 1.5401x over previous
#include <cuda_runtime.h>

#define HID 128
#define TPB 256

using u64 = unsigned long long;

// Packed f32x2 ops (Blackwell): 2 fp32 MACs per issue. ptxas never auto-fuses;
// only the PTX fma.rn.f32x2 path reaches the packed pipe.
static __device__ __forceinline__ u64 ffma2(u64 a, u64 b, u64 c) {
    u64 d;
    asm("fma.rn.f32x2 %0, %1, %2, %3;" : "=l"(d) : "l"(a), "l"(b), "l"(c));
    return d;
}
static __device__ __forceinline__ u64 fadd2(u64 a, u64 b) {
    u64 d;
    asm("add.rn.f32x2 %0, %1, %2;" : "=l"(d) : "l"(a), "l"(b));
    return d;
}
static __device__ __forceinline__ void unpack2(u64 v, float& lo, float& hi) {
    asm("mov.b64 {%0, %1}, %2;" : "=f"(lo), "=f"(hi) : "l"(v));
}
static __device__ __forceinline__ u64 pack2(float lo, float hi) {
    u64 r;
    asm("mov.b64 %0, {%1, %2};" : "=l"(r) : "f"(lo), "f"(hi));
    return r;
}

// W2^T split into 4 quarter-regions by i, each skewed +4 floats (16B) so the
// 4 quads of a warp broadcast from disjoint 16B bank groups (conflict-free
// LDS.128). Region q holds w2q[j*32 + (i - q*32)] = W2[i][j] for i in quad q.
static constexpr int QREG = 32 * HID + 4;               // 4100 floats per region
static constexpr int SMEM_FLOATS = 4 * QREG + 6 * HID;  // + w1 rows, b1, b2, w3

extern __shared__ float smem[];

__global__ void __launch_bounds__(TPB, 2)
sdf_march_kernel(const float* __restrict__ pos, const float* __restrict__ dir,
                 const float* __restrict__ W1, const float* __restrict__ b1,
                 const float* __restrict__ W2, const float* __restrict__ b2,
                 const float* __restrict__ W3, const float* __restrict__ b3,
                 const int* __restrict__ steps_ptr, float* __restrict__ out)
{
    float* s_w2   = smem;                 // 4 * QREG
    float* s_w1r0 = s_w2 + 4 * QREG;
    float* s_w1r1 = s_w1r0 + HID;
    float* s_w1r2 = s_w1r1 + HID;
    float* s_b1   = s_w1r2 + HID;
    float* s_b2   = s_b1 + HID;
    float* s_w3   = s_b2 + HID;

    const int t = threadIdx.x;

    // Stage W2 transposed into quarter regions (coalesced gmem reads).
    for (int idx = t; idx < HID * HID; idx += TPB) {
        const int i = idx >> 7;          // row of W2
        const int j = idx & 127;         // col of W2
        const int q = i >> 5;
        const int io = i & 31;
        s_w2[q * QREG + j * 32 + io] = W2[idx];
    }
    if (t < HID) {
        s_w1r0[t] = W1[t];
        s_w1r1[t] = W1[HID + t];
        s_w1r2[t] = W1[2 * HID + t];
        s_b1[t] = b1[t];
        s_b2[t] = b2[t];
        s_w3[t] = W3[t];
    }
    __syncthreads();

    // Thread quad (t&~3 .. +3) jointly handles 2 rays; each thread owns one
    // quarter of the hidden dimension (32 i-values) for BOTH rays.
    const int gt = blockIdx.x * TPB + t;
    const int q  = t & 3;
    const int grp = gt >> 2;
    const int r0 = grp * 2;
    const int r1 = r0 + 1;

    float px0 = pos[r0 * 3 + 0], py0 = pos[r0 * 3 + 1], pz0 = pos[r0 * 3 + 2];
    float px1 = pos[r1 * 3 + 0], py1 = pos[r1 * 3 + 1], pz1 = pos[r1 * 3 + 2];
    const float dx0 = dir[r0 * 3 + 0], dy0 = dir[r0 * 3 + 1], dz0 = dir[r0 * 3 + 2];
    const float dx1 = dir[r1 * 3 + 0], dy1 = dir[r1 * 3 + 1], dz1 = dir[r1 * 3 + 2];

    const int    ibase = q * 32;
    const float* wbase = s_w2 + q * QREG;
    const float  bias3 = b3[0];
    const int    nsteps = steps_ptr[0];

    // h1 for this thread's 32 i-values, i-pair packed, per ray: 32 u64 regs.
    u64 h1a[16], h1b[16];

    for (int s = 0; s < nsteps; ++s) {
        // ---- Layer 1: h1[i] = relu(p . W1[:,i] + b1[i]) for my 32 i ----
        #pragma unroll
        for (int m = 0; m < 8; ++m) {
            const int i0 = ibase + 4 * m;
            const float4 wa = *(const float4*)(s_w1r0 + i0);
            const float4 wb = *(const float4*)(s_w1r1 + i0);
            const float4 wc = *(const float4*)(s_w1r2 + i0);
            const float4 bb = *(const float4*)(s_b1 + i0);

            const float v00 = fmaxf(fmaf(px0, wa.x, fmaf(py0, wb.x, fmaf(pz0, wc.x, bb.x))), 0.f);
            const float v01 = fmaxf(fmaf(px0, wa.y, fmaf(py0, wb.y, fmaf(pz0, wc.y, bb.y))), 0.f);
            const float v02 = fmaxf(fmaf(px0, wa.z, fmaf(py0, wb.z, fmaf(pz0, wc.z, bb.z))), 0.f);
            const float v03 = fmaxf(fmaf(px0, wa.w, fmaf(py0, wb.w, fmaf(pz0, wc.w, bb.w))), 0.f);
            const float v10 = fmaxf(fmaf(px1, wa.x, fmaf(py1, wb.x, fmaf(pz1, wc.x, bb.x))), 0.f);
            const float v11 = fmaxf(fmaf(px1, wa.y, fmaf(py1, wb.y, fmaf(pz1, wc.y, bb.y))), 0.f);
            const float v12 = fmaxf(fmaf(px1, wa.z, fmaf(py1, wb.z, fmaf(pz1, wc.z, bb.z))), 0.f);
            const float v13 = fmaxf(fmaf(px1, wa.w, fmaf(py1, wb.w, fmaf(pz1, wc.w, bb.w))), 0.f);

            h1a[2 * m]     = pack2(v00, v01);
            h1a[2 * m + 1] = pack2(v02, v03);
            h1b[2 * m]     = pack2(v10, v11);
            h1b[2 * m + 1] = pack2(v12, v13);
        }

        // ---- Layers 2+3 fused: sdf = b3 + sum_j W3[j]*relu(h1 . W2[:,j] + b2[j]) ----
        float sdf0 = bias3, sdf1 = bias3;
        #pragma unroll 1
        for (int j = 0; j < HID; ++j) {
            const ulonglong2* wrow = (const ulonglong2*)(wbase + j * 32);
            u64 a00 = 0, a01 = 0, a10 = 0, a11 = 0;  // 4 independent FFMA2 chains
            #pragma unroll
            for (int m = 0; m < 8; ++m) {
                const ulonglong2 w = wrow[m];  // LDS.128: 4 weights -> 4 FFMA2
                a00 = ffma2(h1a[2 * m],     w.x, a00);
                a01 = ffma2(h1a[2 * m + 1], w.y, a01);
                a10 = ffma2(h1b[2 * m],     w.x, a10);
                a11 = ffma2(h1b[2 * m + 1], w.y, a11);
            }
            const u64 s0 = fadd2(a00, a01);
            const u64 s1 = fadd2(a10, a11);
            float e0, o0, e1, o1;
            unpack2(s0, e0, o0);
            unpack2(s1, e1, o1);
            float q0 = e0 + o0;
            float q1 = e1 + o1;
            // Combine the 4 quarter partials across the thread quad.
            q0 += __shfl_xor_sync(0xffffffffu, q0, 1);
            q0 += __shfl_xor_sync(0xffffffffu, q0, 2);
            q1 += __shfl_xor_sync(0xffffffffu, q1, 1);
            q1 += __shfl_xor_sync(0xffffffffu, q1, 2);
            const float b2j = s_b2[j];
            const float w3j = s_w3[j];
            sdf0 = fmaf(fmaxf(q0 + b2j, 0.f), w3j, sdf0);
            sdf1 = fmaf(fmaxf(q1 + b2j, 0.f), w3j, sdf1);
        }

        // ---- March both rays (all quad members track identical ray state) ----
        px0 = fmaf(sdf0, dx0, px0); py0 = fmaf(sdf0, dy0, py0); pz0 = fmaf(sdf0, dz0, pz0);
        px1 = fmaf(sdf1, dx1, px1); py1 = fmaf(sdf1, dy1, py1); pz1 = fmaf(sdf1, dz1, pz1);
    }

    // Two writers per quad: lane q=0 writes r0, q=1 writes r1.
    if (q == 0) {
        out[r0 * 3 + 0] = px0; out[r0 * 3 + 1] = py0; out[r0 * 3 + 2] = pz0;
    } else if (q == 1) {
        out[r1 * 3 + 0] = px1; out[r1 * 3 + 1] = py1; out[r1 * 3 + 2] = pz1;
    }
}

extern "C" void kernel_launch(void* const* d_in, const int* in_sizes, int n_in,
                              void* d_out, int out_size) {
    const float* pos = (const float*)d_in[0];
    const float* dir = (const float*)d_in[1];
    const float* W1  = (const float*)d_in[2];
    const float* b1  = (const float*)d_in[3];
    const float* W2  = (const float*)d_in[4];
    const float* b2  = (const float*)d_in[5];
    const float* W3  = (const float*)d_in[6];
    const float* b3  = (const float*)d_in[7];
    const int* steps = (const int*)d_in[8];

    const int n_rays = in_sizes[0] / 3;
    // 4 threads per 2 rays -> 2 threads per ray.
    const int n_blocks = (n_rays * 2) / TPB;

    const size_t smem_bytes = SMEM_FLOATS * sizeof(float);
    cudaFuncSetAttribute(sdf_march_kernel,
                         cudaFuncAttributeMaxDynamicSharedMemorySize,
                         (int)smem_bytes);

    sdf_march_kernel<<<n_blocks, TPB, smem_bytes>>>(
        pos, dir, W1, b1, W2, b2, W3, b3, steps, (float*)d_out);
}

// round 6
// speedup vs baseline: 6.9388x; 4.5053x over previous
#include <cuda_runtime.h>
#include <cuda_bf16.h>
#include <cstdint>

#define TPB   256
#define WARPS 8

// ---- smem layout (bytes) ----
// Per-warp A tiles (h1 activations), 32 rows x 128 bf16 cols, 256B rows,
// 16B-chunk XOR swizzle:  hi @ warp*16384, lo @ +8192.
static constexpr int A_OFF   = 0;                  // 8 * 16384 = 128 KB
static constexpr int BH_OFF  = 131072;             // W2^T hi tile, 128x128 bf16 = 32 KB
static constexpr int BL_OFF  = 163840;             // W2^T lo tile, 32 KB
static constexpr int P_OFF   = 196608;             // 256 * float4 ray positions
static constexpr int BW_OFF  = 200704;             // 128 * float2 (b2, w3)
static constexpr int SDF_OFF = 201728;             // 256 * float
static constexpr int SMEM_TOTAL = 202752;

static __device__ __forceinline__ uint32_t smem_u32(const void* p) {
    uint32_t a;
    asm("{ .reg .u64 t; cvta.to.shared.u64 t, %1; cvt.u32.u64 %0, t; }"
        : "=r"(a) : "l"(p));
    return a;
}

static __device__ __forceinline__ void ldsm_x4(uint32_t (&r)[4], uint32_t addr) {
    asm volatile("ldmatrix.sync.aligned.m8n8.x4.shared.b16 {%0,%1,%2,%3}, [%4];"
                 : "=r"(r[0]), "=r"(r[1]), "=r"(r[2]), "=r"(r[3]) : "r"(addr));
}

static __device__ __forceinline__ void mma_bf16(float* d, const uint32_t (&a)[4],
                                                uint32_t b0, uint32_t b1) {
    asm volatile(
        "mma.sync.aligned.m16n8k16.row.col.f32.bf16.bf16.f32 "
        "{%0,%1,%2,%3}, {%4,%5,%6,%7}, {%8,%9}, {%0,%1,%2,%3};"
        : "+f"(d[0]), "+f"(d[1]), "+f"(d[2]), "+f"(d[3])
        : "r"(a[0]), "r"(a[1]), "r"(a[2]), "r"(a[3]), "r"(b0), "r"(b1));
}

// bf16x2 pack of (lo, hi) with rn.
static __device__ __forceinline__ uint32_t bf16x2_rn(float lo, float hi) {
    uint32_t r;
    asm("cvt.rn.bf16x2.f32 %0, %1, %2;" : "=r"(r) : "f"(hi), "f"(lo));
    return r;
}

extern __shared__ char smem[];

__global__ void __launch_bounds__(TPB)
sdf_march_mma(const float* __restrict__ pos, const float* __restrict__ dir,
              const float* __restrict__ W1, const float* __restrict__ b1,
              const float* __restrict__ W2, const float* __restrict__ b2,
              const float* __restrict__ W3, const float* __restrict__ b3,
              const int* __restrict__ steps_ptr, float* __restrict__ out)
{
    const int tid  = threadIdx.x;
    const int wid  = tid >> 5;
    const int lane = tid & 31;
    const uint32_t sbase = smem_u32(smem);

    // ---- Stage B = W2^T with bf16 hi/lo truncation split, swizzled ----
    // B^T[n][k] row-major: row n (256B), chunk = k/8, swz chunk ^= n&7.
    for (int idx = tid; idx < 128 * 128; idx += TPB) {
        const int k = idx >> 7;    // W2 row index i (reduction dim)
        const int n = idx & 127;   // W2 col index j
        const float v = W2[idx];
        const uint32_t vb = __float_as_uint(v);
        const uint32_t off = (uint32_t)n * 256u
                           + (uint32_t)(((k >> 3) ^ (n & 7)) << 4)
                           + (uint32_t)((k & 7) << 1);
        *(unsigned short*)(smem + BH_OFF + off) = (unsigned short)(vb >> 16);
        const float lo = v - __uint_as_float(vb & 0xFFFF0000u);
        *(__nv_bfloat16*)(smem + BL_OFF + off) = __float2bfloat16(lo);
    }
    if (tid < 128) {
        ((float2*)(smem + BW_OFF))[tid] = make_float2(b2[tid], W3[tid]);
    }

    // ---- Ray state: lane owns ray (cta*256 + wid*32 + lane) ----
    const int ray = blockIdx.x * TPB + tid;
    float px = pos[ray * 3 + 0], py = pos[ray * 3 + 1], pz = pos[ray * 3 + 2];
    const float dx = dir[ray * 3 + 0], dy = dir[ray * 3 + 1], dz = dir[ray * 3 + 2];
    ((float4*)(smem + P_OFF))[tid] = make_float4(px, py, pz, 0.f);

    // ---- Layer-1 constants: this lane computes i in [lane*4, lane*4+4) ----
    const int i0 = lane * 4;
    float w1x[4], w1y[4], w1z[4], b1c[4];
    #pragma unroll
    for (int c = 0; c < 4; ++c) {
        w1x[c] = W1[i0 + c];
        w1y[c] = W1[128 + i0 + c];
        w1z[c] = W1[256 + i0 + c];
        b1c[c] = b1[i0 + c];
    }
    const float bias3 = b3[0];
    const int nsteps = steps_ptr[0];

    __syncthreads();  // B tiles, bw, initial p visible

    // ---- Precomputed addresses ----
    const uint32_t aw_hi = sbase + A_OFF + (uint32_t)wid * 16384u;
    const uint32_t aw_lo = aw_hi + 8192u;
    // Layer-1 store: lane writes 8B at chunk lane>>1 (swizzled per row).
    const uint32_t st_ch   = (uint32_t)(lane >> 1);
    const uint32_t st_half = (uint32_t)((lane & 1) << 3);
    // ldmatrix A: row = lane&15 (+16*mt), chunk = 2k + (lane>>4), swz ^ (row&7).
    const uint32_t a_row  = (uint32_t)(lane & 15);
    const uint32_t a_rx   = a_row & 7u;
    const uint32_t a_cs   = (uint32_t)(lane >> 4);
    const uint32_t a_rowb = a_row * 256u;
    // ldmatrix B: n = 16nt + (lane&7) + ((lane>>4)<<3), chunk = 2k + ((lane>>3)&1).
    const uint32_t b_rx   = (uint32_t)(lane & 7);
    const uint32_t b_cs   = (uint32_t)((lane >> 3) & 1);
    const uint32_t b_rowb = ((uint32_t)(lane & 7) + (uint32_t)(((lane >> 4) & 1) << 3)) * 256u;
    const uint32_t bh_base = sbase + BH_OFF + b_rowb;
    const uint32_t bl_base = sbase + BL_OFF + b_rowb;

    float4* sp   = (float4*)(smem + P_OFF) + wid * 32;
    float*  ssdf = (float*)(smem + SDF_OFF) + wid * 32;
    const float2* sbw = (const float2*)(smem + BW_OFF);

    #pragma unroll 1
    for (int s = 0; s < nsteps; ++s) {
        // ================= Layer 1: h1 = relu(p.W1 + b1) -> A tiles =========
        #pragma unroll 2
        for (int r = 0; r < 32; ++r) {
            const float4 P = sp[r];  // warp broadcast
            float v[4];
            #pragma unroll
            for (int c = 0; c < 4; ++c) {
                v[c] = fmaxf(fmaf(P.x, w1x[c], fmaf(P.y, w1y[c],
                             fmaf(P.z, w1z[c], b1c[c]))), 0.f);
            }
            const uint32_t u0 = __float_as_uint(v[0]);
            const uint32_t u1 = __float_as_uint(v[1]);
            const uint32_t u2 = __float_as_uint(v[2]);
            const uint32_t u3 = __float_as_uint(v[3]);
            uint2 hi;
            hi.x = __byte_perm(u0, u1, 0x7632);  // {bf16(v0), bf16(v1)} truncated
            hi.y = __byte_perm(u2, u3, 0x7632);
            uint2 lo;
            lo.x = bf16x2_rn(v[0] - __uint_as_float(u0 & 0xFFFF0000u),
                             v[1] - __uint_as_float(u1 & 0xFFFF0000u));
            lo.y = bf16x2_rn(v[2] - __uint_as_float(u2 & 0xFFFF0000u),
                             v[3] - __uint_as_float(u3 & 0xFFFF0000u));
            const uint32_t off = (uint32_t)r * 256u
                               + ((st_ch ^ (uint32_t)(r & 7)) << 4) + st_half;
            *(uint2*)(smem + (aw_hi - sbase) + off) = hi;
            *(uint2*)(smem + (aw_lo - sbase) + off) = lo;
        }
        // Same-warp smem program order: no fence needed before ldmatrix.

        // ================= Layer 2: acc = Ah.Bh + Al.Bh + Ah.Bl =============
        float acc[2][16][4];
        #pragma unroll
        for (int mt = 0; mt < 2; ++mt)
            #pragma unroll
            for (int nt = 0; nt < 16; ++nt)
                #pragma unroll
                for (int c = 0; c < 4; ++c) acc[mt][nt][c] = 0.f;

        #pragma unroll 1
        for (int k = 0; k < 8; ++k) {
            const uint32_t a_sw = ((2u * (uint32_t)k + a_cs) ^ a_rx) << 4;
            uint32_t ah[2][4], al[2][4];
            ldsm_x4(ah[0], aw_hi + a_rowb + a_sw);
            ldsm_x4(ah[1], aw_hi + 4096u + a_rowb + a_sw);
            ldsm_x4(al[0], aw_lo + a_rowb + a_sw);
            ldsm_x4(al[1], aw_lo + 4096u + a_rowb + a_sw);
            const uint32_t b_sw = ((2u * (uint32_t)k + b_cs) ^ b_rx) << 4;
            #pragma unroll
            for (int n2 = 0; n2 < 8; ++n2) {   // n16 tile -> two n8 tiles
                uint32_t bh[4], bl[4];
                ldsm_x4(bh, bh_base + (uint32_t)n2 * 4096u + b_sw);
                ldsm_x4(bl, bl_base + (uint32_t)n2 * 4096u + b_sw);
                #pragma unroll
                for (int mt = 0; mt < 2; ++mt) {
                    mma_bf16(acc[mt][2 * n2],     ah[mt], bh[0], bh[1]);
                    mma_bf16(acc[mt][2 * n2],     al[mt], bh[0], bh[1]);
                    mma_bf16(acc[mt][2 * n2],     ah[mt], bl[0], bl[1]);
                    mma_bf16(acc[mt][2 * n2 + 1], ah[mt], bh[2], bh[3]);
                    mma_bf16(acc[mt][2 * n2 + 1], al[mt], bh[2], bh[3]);
                    mma_bf16(acc[mt][2 * n2 + 1], ah[mt], bl[2], bl[3]);
                }
            }
        }

        // ================= Epilogue: sdf = b3 + sum relu(h2+b2)*w3 ==========
        // acc[mt][nt][c]: rows {lane/4, lane/4+8} (+16*mt), cols nt*8+2*(lane&3)+{0,1}
        float part[4] = {0.f, 0.f, 0.f, 0.f};
        #pragma unroll
        for (int nt = 0; nt < 16; ++nt) {
            const int n0 = nt * 8 + 2 * (lane & 3);
            const float2 bw0 = sbw[n0];
            const float2 bw1 = sbw[n0 + 1];
            #pragma unroll
            for (int mt = 0; mt < 2; ++mt) {
                const float* c = acc[mt][nt];
                part[2 * mt]     = fmaf(fmaxf(c[0] + bw0.x, 0.f), bw0.y, part[2 * mt]);
                part[2 * mt]     = fmaf(fmaxf(c[1] + bw1.x, 0.f), bw1.y, part[2 * mt]);
                part[2 * mt + 1] = fmaf(fmaxf(c[2] + bw0.x, 0.f), bw0.y, part[2 * mt + 1]);
                part[2 * mt + 1] = fmaf(fmaxf(c[3] + bw1.x, 0.f), bw1.y, part[2 * mt + 1]);
            }
        }
        #pragma unroll
        for (int c = 0; c < 4; ++c) {
            part[c] += __shfl_xor_sync(0xffffffffu, part[c], 1);
            part[c] += __shfl_xor_sync(0xffffffffu, part[c], 2);
        }
        if ((lane & 3) == 0) {
            const int q = lane >> 2;
            ssdf[q]      = part[0] + bias3;   // ray q      (mt0, row q)
            ssdf[q + 8]  = part[1] + bias3;   // ray q+8    (mt0, row q+8)
            ssdf[q + 16] = part[2] + bias3;   // ray q+16   (mt1, row q)
            ssdf[q + 24] = part[3] + bias3;   // ray q+24
        }
        __syncwarp();

        // ================= March + publish p ================================
        const float sdf = ssdf[lane];
        px = fmaf(sdf, dx, px);
        py = fmaf(sdf, dy, py);
        pz = fmaf(sdf, dz, pz);
        sp[lane] = make_float4(px, py, pz, 0.f);
        __syncwarp();
    }

    out[ray * 3 + 0] = px;
    out[ray * 3 + 1] = py;
    out[ray * 3 + 2] = pz;
}

extern "C" void kernel_launch(void* const* d_in, const int* in_sizes, int n_in,
                              void* d_out, int out_size) {
    const float* pos = (const float*)d_in[0];
    const float* dir = (const float*)d_in[1];
    const float* W1  = (const float*)d_in[2];
    const float* b1  = (const float*)d_in[3];
    const float* W2  = (const float*)d_in[4];
    const float* b2  = (const float*)d_in[5];
    const float* W3  = (const float*)d_in[6];
    const float* b3  = (const float*)d_in[7];
    const int* steps = (const int*)d_in[8];

    const int n_rays   = in_sizes[0] / 3;
    const int n_blocks = n_rays / TPB;  // 256 rays per CTA

    cudaFuncSetAttribute(sdf_march_mma,
                         cudaFuncAttributeMaxDynamicSharedMemorySize, SMEM_TOTAL);

    sdf_march_mma<<<n_blocks, TPB, SMEM_TOTAL>>>(
        pos, dir, W1, b1, W2, b2, W3, b3, steps, (float*)d_out);
}

// round 7
// speedup vs baseline: 8.7208x; 1.2568x over previous
#include <cuda_runtime.h>
#include <cuda_bf16.h>
#include <cstdint>

#define TPB   256
#define WARPS 8

// ---- smem layout (bytes) ----
// Per-warp A tiles (h1 activations), 32 rows x 128 bf16 cols, 256B rows,
// 16B-chunk XOR swizzle:  hi @ warp*16384, lo @ +8192.
// B = rn(W2^T) single bf16 tile (A carries the exact hi/lo split; 2-product
// compensation: D = Ah*B + Al*B, element err ~2^-9 from B rounding only).
static constexpr int A_OFF   = 0;                  // 8 * 16384 = 128 KB
static constexpr int BH_OFF  = 131072;             // W2^T rn tile, 128x128 bf16 = 32 KB
static constexpr int P_OFF   = 163840;             // 256 * float4 ray positions
static constexpr int BW_OFF  = 167936;             // 128 * float2 (b2, w3)
static constexpr int SDF_OFF = 168960;             // 256 * float
static constexpr int SMEM_TOTAL = 169984;

static __device__ __forceinline__ uint32_t smem_u32(const void* p) {
    uint32_t a;
    asm("{ .reg .u64 t; cvta.to.shared.u64 t, %1; cvt.u32.u64 %0, t; }"
        : "=r"(a) : "l"(p));
    return a;
}

static __device__ __forceinline__ void ldsm_x4(uint32_t (&r)[4], uint32_t addr) {
    asm volatile("ldmatrix.sync.aligned.m8n8.x4.shared.b16 {%0,%1,%2,%3}, [%4];"
                 : "=r"(r[0]), "=r"(r[1]), "=r"(r[2]), "=r"(r[3]) : "r"(addr));
}

static __device__ __forceinline__ void mma_bf16(float* d, const uint32_t (&a)[4],
                                                uint32_t b0, uint32_t b1) {
    asm volatile(
        "mma.sync.aligned.m16n8k16.row.col.f32.bf16.bf16.f32 "
        "{%0,%1,%2,%3}, {%4,%5,%6,%7}, {%8,%9}, {%0,%1,%2,%3};"
        : "+f"(d[0]), "+f"(d[1]), "+f"(d[2]), "+f"(d[3])
        : "r"(a[0]), "r"(a[1]), "r"(a[2]), "r"(a[3]), "r"(b0), "r"(b1));
}

// bf16x2 pack of (lo, hi) with rn.
static __device__ __forceinline__ uint32_t bf16x2_rn(float lo, float hi) {
    uint32_t r;
    asm("cvt.rn.bf16x2.f32 %0, %1, %2;" : "=r"(r) : "f"(hi), "f"(lo));
    return r;
}

extern __shared__ char smem[];

__global__ void __launch_bounds__(TPB)
sdf_march_mma(const float* __restrict__ pos, const float* __restrict__ dir,
              const float* __restrict__ W1, const float* __restrict__ b1,
              const float* __restrict__ W2, const float* __restrict__ b2,
              const float* __restrict__ W3, const float* __restrict__ b3,
              const int* __restrict__ steps_ptr, float* __restrict__ out)
{
    const int tid  = threadIdx.x;
    const int wid  = tid >> 5;
    const int lane = tid & 31;
    const uint32_t sbase = smem_u32(smem);

    // ---- Stage B = rn(W2^T), swizzled ----
    // B^T[n][k] row-major: row n (256B), chunk = k/8, swz chunk ^= n&7.
    for (int idx = tid; idx < 128 * 128; idx += TPB) {
        const int k = idx >> 7;    // W2 row index i (reduction dim)
        const int n = idx & 127;   // W2 col index j
        const uint32_t off = (uint32_t)n * 256u
                           + (uint32_t)(((k >> 3) ^ (n & 7)) << 4)
                           + (uint32_t)((k & 7) << 1);
        *(__nv_bfloat16*)(smem + BH_OFF + off) = __float2bfloat16(W2[idx]);
    }
    if (tid < 128) {
        ((float2*)(smem + BW_OFF))[tid] = make_float2(b2[tid], W3[tid]);
    }

    // ---- Ray state: lane owns ray (cta*256 + wid*32 + lane) ----
    const int ray = blockIdx.x * TPB + tid;
    float px = pos[ray * 3 + 0], py = pos[ray * 3 + 1], pz = pos[ray * 3 + 2];
    const float dx = dir[ray * 3 + 0], dy = dir[ray * 3 + 1], dz = dir[ray * 3 + 2];
    ((float4*)(smem + P_OFF))[tid] = make_float4(px, py, pz, 0.f);

    // ---- Layer-1 constants: this lane computes i in [lane*4, lane*4+4) ----
    const int i0 = lane * 4;
    float w1x[4], w1y[4], w1z[4], b1c[4];
    #pragma unroll
    for (int c = 0; c < 4; ++c) {
        w1x[c] = W1[i0 + c];
        w1y[c] = W1[128 + i0 + c];
        w1z[c] = W1[256 + i0 + c];
        b1c[c] = b1[i0 + c];
    }
    const float bias3 = b3[0];
    const int nsteps = steps_ptr[0];

    __syncthreads();  // B tile, bw, initial p visible

    // ---- Precomputed addresses ----
    const uint32_t aw_hi = sbase + A_OFF + (uint32_t)wid * 16384u;
    const uint32_t aw_lo = aw_hi + 8192u;
    // Layer-1 store: lane writes 8B at chunk lane>>1 (swizzled per row).
    const uint32_t st_ch   = (uint32_t)(lane >> 1);
    const uint32_t st_half = (uint32_t)((lane & 1) << 3);
    // ldmatrix A: row = lane&15 (+16*mt), chunk = 2k + (lane>>4), swz ^ (row&7).
    const uint32_t a_row  = (uint32_t)(lane & 15);
    const uint32_t a_rx   = a_row & 7u;
    const uint32_t a_cs   = (uint32_t)(lane >> 4);
    const uint32_t a_rowb = a_row * 256u;
    // ldmatrix B: n = 16nt + (lane&7) + ((lane>>4)<<3), chunk = 2k + ((lane>>3)&1).
    const uint32_t b_rx   = (uint32_t)(lane & 7);
    const uint32_t b_cs   = (uint32_t)((lane >> 3) & 1);
    const uint32_t b_rowb = ((uint32_t)(lane & 7) + (uint32_t)(((lane >> 4) & 1) << 3)) * 256u;
    const uint32_t bh_base = sbase + BH_OFF + b_rowb;

    float4* sp   = (float4*)(smem + P_OFF) + wid * 32;
    float*  ssdf = (float*)(smem + SDF_OFF) + wid * 32;
    const float2* sbw = (const float2*)(smem + BW_OFF);

    #pragma unroll 1
    for (int s = 0; s < nsteps; ++s) {
        // ================= Layer 1: h1 = relu(p.W1 + b1) -> A tiles =========
        #pragma unroll 2
        for (int r = 0; r < 32; ++r) {
            const float4 P = sp[r];  // warp broadcast
            float v[4];
            #pragma unroll
            for (int c = 0; c < 4; ++c) {
                v[c] = fmaxf(fmaf(P.x, w1x[c], fmaf(P.y, w1y[c],
                             fmaf(P.z, w1z[c], b1c[c]))), 0.f);
            }
            const uint32_t u0 = __float_as_uint(v[0]);
            const uint32_t u1 = __float_as_uint(v[1]);
            const uint32_t u2 = __float_as_uint(v[2]);
            const uint32_t u3 = __float_as_uint(v[3]);
            uint2 hi;
            hi.x = __byte_perm(u0, u1, 0x7632);  // {bf16(v0), bf16(v1)} truncated
            hi.y = __byte_perm(u2, u3, 0x7632);
            uint2 lo;
            lo.x = bf16x2_rn(v[0] - __uint_as_float(u0 & 0xFFFF0000u),
                             v[1] - __uint_as_float(u1 & 0xFFFF0000u));
            lo.y = bf16x2_rn(v[2] - __uint_as_float(u2 & 0xFFFF0000u),
                             v[3] - __uint_as_float(u3 & 0xFFFF0000u));
            const uint32_t off = (uint32_t)r * 256u
                               + ((st_ch ^ (uint32_t)(r & 7)) << 4) + st_half;
            *(uint2*)(smem + (aw_hi - sbase) + off) = hi;
            *(uint2*)(smem + (aw_lo - sbase) + off) = lo;
        }
        // Same-warp smem program order: no fence needed before ldmatrix.

        // ================= Layer 2: acc = Ah.B + Al.B (A exact split) =======
        float acc[2][16][4];
        #pragma unroll
        for (int mt = 0; mt < 2; ++mt)
            #pragma unroll
            for (int nt = 0; nt < 16; ++nt)
                #pragma unroll
                for (int c = 0; c < 4; ++c) acc[mt][nt][c] = 0.f;

        #pragma unroll 1
        for (int k = 0; k < 8; ++k) {
            const uint32_t a_sw = ((2u * (uint32_t)k + a_cs) ^ a_rx) << 4;
            uint32_t ah[2][4], al[2][4];
            ldsm_x4(ah[0], aw_hi + a_rowb + a_sw);
            ldsm_x4(ah[1], aw_hi + 4096u + a_rowb + a_sw);
            ldsm_x4(al[0], aw_lo + a_rowb + a_sw);
            ldsm_x4(al[1], aw_lo + 4096u + a_rowb + a_sw);
            const uint32_t b_sw = ((2u * (uint32_t)k + b_cs) ^ b_rx) << 4;
            #pragma unroll
            for (int n2 = 0; n2 < 8; ++n2) {   // n16 tile -> two n8 tiles
                uint32_t bh[4];
                ldsm_x4(bh, bh_base + (uint32_t)n2 * 4096u + b_sw);
                #pragma unroll
                for (int mt = 0; mt < 2; ++mt) {
                    mma_bf16(acc[mt][2 * n2],     ah[mt], bh[0], bh[1]);
                    mma_bf16(acc[mt][2 * n2],     al[mt], bh[0], bh[1]);
                    mma_bf16(acc[mt][2 * n2 + 1], ah[mt], bh[2], bh[3]);
                    mma_bf16(acc[mt][2 * n2 + 1], al[mt], bh[2], bh[3]);
                }
            }
        }

        // ================= Epilogue: sdf = b3 + sum relu(h2+b2)*w3 ==========
        // acc[mt][nt][c]: rows {lane/4, lane/4+8} (+16*mt), cols nt*8+2*(lane&3)+{0,1}
        float part[4] = {0.f, 0.f, 0.f, 0.f};
        #pragma unroll
        for (int nt = 0; nt < 16; ++nt) {
            const int n0 = nt * 8 + 2 * (lane & 3);
            const float2 bw0 = sbw[n0];
            const float2 bw1 = sbw[n0 + 1];
            #pragma unroll
            for (int mt = 0; mt < 2; ++mt) {
                const float* c = acc[mt][nt];
                part[2 * mt]     = fmaf(fmaxf(c[0] + bw0.x, 0.f), bw0.y, part[2 * mt]);
                part[2 * mt]     = fmaf(fmaxf(c[1] + bw1.x, 0.f), bw1.y, part[2 * mt]);
                part[2 * mt + 1] = fmaf(fmaxf(c[2] + bw0.x, 0.f), bw0.y, part[2 * mt + 1]);
                part[2 * mt + 1] = fmaf(fmaxf(c[3] + bw1.x, 0.f), bw1.y, part[2 * mt + 1]);
            }
        }
        #pragma unroll
        for (int c = 0; c < 4; ++c) {
            part[c] += __shfl_xor_sync(0xffffffffu, part[c], 1);
            part[c] += __shfl_xor_sync(0xffffffffu, part[c], 2);
        }
        if ((lane & 3) == 0) {
            const int q = lane >> 2;
            ssdf[q]      = part[0] + bias3;   // ray q      (mt0, row q)
            ssdf[q + 8]  = part[1] + bias3;   // ray q+8    (mt0, row q+8)
            ssdf[q + 16] = part[2] + bias3;   // ray q+16   (mt1, row q)
            ssdf[q + 24] = part[3] + bias3;   // ray q+24
        }
        __syncwarp();

        // ================= March + publish p ================================
        const float sdf = ssdf[lane];
        px = fmaf(sdf, dx, px);
        py = fmaf(sdf, dy, py);
        pz = fmaf(sdf, dz, pz);
        sp[lane] = make_float4(px, py, pz, 0.f);
        __syncwarp();
    }

    out[ray * 3 + 0] = px;
    out[ray * 3 + 1] = py;
    out[ray * 3 + 2] = pz;
}

extern "C" void kernel_launch(void* const* d_in, const int* in_sizes, int n_in,
                              void* d_out, int out_size) {
    const float* pos = (const float*)d_in[0];
    const float* dir = (const float*)d_in[1];
    const float* W1  = (const float*)d_in[2];
    const float* b1  = (const float*)d_in[3];
    const float* W2  = (const float*)d_in[4];
    const float* b2  = (const float*)d_in[5];
    const float* W3  = (const float*)d_in[6];
    const float* b3  = (const float*)d_in[7];
    const int* steps = (const int*)d_in[8];

    const int n_rays   = in_sizes[0] / 3;
    const int n_blocks = n_rays / TPB;  // 256 rays per CTA

    cudaFuncSetAttribute(sdf_march_mma,
                         cudaFuncAttributeMaxDynamicSharedMemorySize, SMEM_TOTAL);

    sdf_march_mma<<<n_blocks, TPB, SMEM_TOTAL>>>(
        pos, dir, W1, b1, W2, b2, W3, b3, steps, (float*)d_out);
}

// round 9
// speedup vs baseline: 13.2764x; 1.5224x over previous
#include <cuda_runtime.h>
#include <cuda_bf16.h>
#include <cstdint>

#define TPB   256
#define WARPS 8

// ---- smem layout (bytes) ----
// Per-warp A tile (h1 activations, rn bf16), 32 rows x 128 cols, 256B rows,
// 16B-chunk XOR swizzle. Single-product bf16 MMA: D = rn(A).rn(B); measured
// error attenuation (~30x from element to final) puts rel_err ~1.4e-4.
static constexpr int A_OFF   = 0;                  // 8 * 8192 = 64 KB
static constexpr int BH_OFF  = 65536;              // W2^T rn tile, 128x128 bf16 = 32 KB
static constexpr int P_OFF   = 98304;              // 256 * float4 ray positions
static constexpr int BW_OFF  = 102400;             // 128 * float2 (b2, w3)
static constexpr int SDF_OFF = 103424;             // 256 * float
static constexpr int SMEM_TOTAL = 104448;

static __device__ __forceinline__ uint32_t smem_u32(const void* p) {
    uint32_t a;
    asm("{ .reg .u64 t; cvta.to.shared.u64 t, %1; cvt.u32.u64 %0, t; }"
        : "=r"(a) : "l"(p));
    return a;
}

static __device__ __forceinline__ void ldsm_x4(uint32_t (&r)[4], uint32_t addr) {
    asm volatile("ldmatrix.sync.aligned.m8n8.x4.shared.b16 {%0,%1,%2,%3}, [%4];"
                 : "=r"(r[0]), "=r"(r[1]), "=r"(r[2]), "=r"(r[3]) : "r"(addr));
}

static __device__ __forceinline__ void mma_bf16(float* d, const uint32_t (&a)[4],
                                                uint32_t b0, uint32_t b1) {
    asm volatile(
        "mma.sync.aligned.m16n8k16.row.col.f32.bf16.bf16.f32 "
        "{%0,%1,%2,%3}, {%4,%5,%6,%7}, {%8,%9}, {%0,%1,%2,%3};"
        : "+f"(d[0]), "+f"(d[1]), "+f"(d[2]), "+f"(d[3])
        : "r"(a[0]), "r"(a[1]), "r"(a[2]), "r"(a[3]), "r"(b0), "r"(b1));
}

// bf16x2 pack of (lo, hi) with rn.
static __device__ __forceinline__ uint32_t bf16x2_rn(float lo, float hi) {
    uint32_t r;
    asm("cvt.rn.bf16x2.f32 %0, %1, %2;" : "=r"(r) : "f"(hi), "f"(lo));
    return r;
}

extern __shared__ char smem[];

__global__ void __launch_bounds__(TPB)
sdf_march_mma(const float* __restrict__ pos, const float* __restrict__ dir,
              const float* __restrict__ W1, const float* __restrict__ b1,
              const float* __restrict__ W2, const float* __restrict__ b2,
              const float* __restrict__ W3, const float* __restrict__ b3,
              const int* __restrict__ steps_ptr, float* __restrict__ out)
{
    const int tid  = threadIdx.x;
    const int wid  = tid >> 5;
    const int lane = tid & 31;
    const uint32_t sbase = smem_u32(smem);

    // ---- Stage B = rn(W2^T), swizzled ----
    // B^T[n][k] row-major: row n (256B), chunk = k/8, swz chunk ^= n&7.
    for (int idx = tid; idx < 128 * 128; idx += TPB) {
        const int k = idx >> 7;    // W2 row index i (reduction dim)
        const int n = idx & 127;   // W2 col index j
        const uint32_t off = (uint32_t)n * 256u
                           + (uint32_t)(((k >> 3) ^ (n & 7)) << 4)
                           + (uint32_t)((k & 7) << 1);
        *(__nv_bfloat16*)(smem + BH_OFF + off) = __float2bfloat16(W2[idx]);
    }
    if (tid < 128) {
        ((float2*)(smem + BW_OFF))[tid] = make_float2(b2[tid], W3[tid]);
    }

    // ---- Ray state: lane owns ray (cta*256 + wid*32 + lane) ----
    const int ray = blockIdx.x * TPB + tid;
    float px = pos[ray * 3 + 0], py = pos[ray * 3 + 1], pz = pos[ray * 3 + 2];
    const float dx = dir[ray * 3 + 0], dy = dir[ray * 3 + 1], dz = dir[ray * 3 + 2];
    ((float4*)(smem + P_OFF))[tid] = make_float4(px, py, pz, 0.f);

    // ---- Layer-1 constants: this lane computes i in [lane*4, lane*4+4) ----
    const int i0 = lane * 4;
    float w1x[4], w1y[4], w1z[4], b1c[4];
    #pragma unroll
    for (int c = 0; c < 4; ++c) {
        w1x[c] = W1[i0 + c];
        w1y[c] = W1[128 + i0 + c];
        w1z[c] = W1[256 + i0 + c];
        b1c[c] = b1[i0 + c];
    }
    const float bias3 = b3[0];
    const int nsteps = steps_ptr[0];

    __syncthreads();  // B tile, bw, initial p visible

    // ---- Precomputed addresses ----
    const uint32_t aw = sbase + A_OFF + (uint32_t)wid * 8192u;
    // Layer-1 store: lane writes 8B at chunk lane>>1 (swizzled per row).
    const uint32_t st_ch   = (uint32_t)(lane >> 1);
    const uint32_t st_half = (uint32_t)((lane & 1) << 3);
    // ldmatrix A: row = lane&15 (+16*mt), chunk = 2k + (lane>>4), swz ^ (row&7).
    const uint32_t a_row  = (uint32_t)(lane & 15);
    const uint32_t a_rx   = a_row & 7u;
    const uint32_t a_cs   = (uint32_t)(lane >> 4);
    const uint32_t a_rowb = a_row * 256u;
    // ldmatrix B: n = 16nt + (lane&7) + ((lane>>4)<<3), chunk = 2k + ((lane>>3)&1).
    const uint32_t b_rx   = (uint32_t)(lane & 7);
    const uint32_t b_cs   = (uint32_t)((lane >> 3) & 1);
    const uint32_t b_rowb = ((uint32_t)(lane & 7) + (uint32_t)(((lane >> 4) & 1) << 3)) * 256u;
    const uint32_t bh_base = sbase + BH_OFF + b_rowb;

    float4* sp   = (float4*)(smem + P_OFF) + wid * 32;
    float*  ssdf = (float*)(smem + SDF_OFF) + wid * 32;
    const float2* sbw = (const float2*)(smem + BW_OFF);

    #pragma unroll 1
    for (int s = 0; s < nsteps; ++s) {
        // ================= Layer 1: h1 = relu(p.W1 + b1) -> A tile ==========
        #pragma unroll 2
        for (int r = 0; r < 32; ++r) {
            const float4 P = sp[r];  // warp broadcast
            float v[4];
            #pragma unroll
            for (int c = 0; c < 4; ++c) {
                v[c] = fmaxf(fmaf(P.x, w1x[c], fmaf(P.y, w1y[c],
                             fmaf(P.z, w1z[c], b1c[c]))), 0.f);
            }
            uint2 pk;
            pk.x = bf16x2_rn(v[0], v[1]);
            pk.y = bf16x2_rn(v[2], v[3]);
            const uint32_t off = (uint32_t)r * 256u
                               + ((st_ch ^ (uint32_t)(r & 7)) << 4) + st_half;
            *(uint2*)(smem + (aw - sbase) + off) = pk;
        }
        // Same-warp smem program order: no fence needed before ldmatrix.

        // ================= Layer 2: acc = rn(A).rn(B) =======================
        float acc[2][16][4];
        #pragma unroll
        for (int mt = 0; mt < 2; ++mt)
            #pragma unroll
            for (int nt = 0; nt < 16; ++nt)
                #pragma unroll
                for (int c = 0; c < 4; ++c) acc[mt][nt][c] = 0.f;

        #pragma unroll 1
        for (int k = 0; k < 8; ++k) {
            const uint32_t a_sw = ((2u * (uint32_t)k + a_cs) ^ a_rx) << 4;
            uint32_t ah[2][4];
            ldsm_x4(ah[0], aw + a_rowb + a_sw);
            ldsm_x4(ah[1], aw + 4096u + a_rowb + a_sw);
            const uint32_t b_sw = ((2u * (uint32_t)k + b_cs) ^ b_rx) << 4;
            #pragma unroll
            for (int n2 = 0; n2 < 8; ++n2) {   // n16 tile -> two n8 tiles
                uint32_t bh[4];
                ldsm_x4(bh, bh_base + (uint32_t)n2 * 4096u + b_sw);
                #pragma unroll
                for (int mt = 0; mt < 2; ++mt) {
                    mma_bf16(acc[mt][2 * n2],     ah[mt], bh[0], bh[1]);
                    mma_bf16(acc[mt][2 * n2 + 1], ah[mt], bh[2], bh[3]);
                }
            }
        }

        // ================= Epilogue: sdf = b3 + sum relu(h2+b2)*w3 ==========
        // acc[mt][nt][c]: rows {lane/4, lane/4+8} (+16*mt), cols nt*8+2*(lane&3)+{0,1}
        float part[4] = {0.f, 0.f, 0.f, 0.f};
        #pragma unroll
        for (int nt = 0; nt < 16; ++nt) {
            const int n0 = nt * 8 + 2 * (lane & 3);
            const float2 bw0 = sbw[n0];
            const float2 bw1 = sbw[n0 + 1];
            #pragma unroll
            for (int mt = 0; mt < 2; ++mt) {
                const float* c = acc[mt][nt];
                part[2 * mt]     = fmaf(fmaxf(c[0] + bw0.x, 0.f), bw0.y, part[2 * mt]);
                part[2 * mt]     = fmaf(fmaxf(c[1] + bw1.x, 0.f), bw1.y, part[2 * mt]);
                part[2 * mt + 1] = fmaf(fmaxf(c[2] + bw0.x, 0.f), bw0.y, part[2 * mt + 1]);
                part[2 * mt + 1] = fmaf(fmaxf(c[3] + bw1.x, 0.f), bw1.y, part[2 * mt + 1]);
            }
        }
        #pragma unroll
        for (int c = 0; c < 4; ++c) {
            part[c] += __shfl_xor_sync(0xffffffffu, part[c], 1);
            part[c] += __shfl_xor_sync(0xffffffffu, part[c], 2);
        }
        if ((lane & 3) == 0) {
            const int q = lane >> 2;
            ssdf[q]      = part[0] + bias3;   // ray q      (mt0, row q)
            ssdf[q + 8]  = part[1] + bias3;   // ray q+8    (mt0, row q+8)
            ssdf[q + 16] = part[2] + bias3;   // ray q+16   (mt1, row q)
            ssdf[q + 24] = part[3] + bias3;   // ray q+24
        }
        __syncwarp();

        // ================= March + publish p ================================
        const float sdf = ssdf[lane];
        px = fmaf(sdf, dx, px);
        py = fmaf(sdf, dy, py);
        pz = fmaf(sdf, dz, pz);
        sp[lane] = make_float4(px, py, pz, 0.f);
        __syncwarp();
    }

    out[ray * 3 + 0] = px;
    out[ray * 3 + 1] = py;
    out[ray * 3 + 2] = pz;
}

extern "C" void kernel_launch(void* const* d_in, const int* in_sizes, int n_in,
                              void* d_out, int out_size) {
    const float* pos = (const float*)d_in[0];
    const float* dir = (const float*)d_in[1];
    const float* W1  = (const float*)d_in[2];
    const float* b1  = (const float*)d_in[3];
    const float* W2  = (const float*)d_in[4];
    const float* b2  = (const float*)d_in[5];
    const float* W3  = (const float*)d_in[6];
    const float* b3  = (const float*)d_in[7];
    const int* steps = (const int*)d_in[8];

    const int n_rays   = in_sizes[0] / 3;
    const int n_blocks = n_rays / TPB;  // 256 rays per CTA

    cudaFuncSetAttribute(sdf_march_mma,
                         cudaFuncAttributeMaxDynamicSharedMemorySize, SMEM_TOTAL);

    sdf_march_mma<<<n_blocks, TPB, SMEM_TOTAL>>>(
        pos, dir, W1, b1, W2, b2, W3, b3, steps, (float*)d_out);
}